// round 1
// baseline (speedup 1.0000x reference)
#include <cuda_runtime.h>
#include <math.h>

#define BATCH   16
#define N_PEP   128
#define M_PRO   2048
#define HEADS   8
#define DH      96
#define INNER   768
#define SCALE_F 0.10206207261596577f   /* 96^-0.5 */
#define NEG_F   -1000000.0f
#define EPS_F   1e-5f

// ---------------- scratch (device globals; no allocations) ----------------
__device__ float g_q   [BATCH * N_PEP * INNER];
__device__ float g_k   [BATCH * M_PRO * INNER];
__device__ float g_vp  [BATCH * M_PRO * INNER];   // v_prot
__device__ float g_vq  [BATCH * N_PEP * INNER];   // v_pep
__device__ float g_cp  [BATCH * N_PEP * INNER];   // ctx peptide-side (attn @ v_prot)
__device__ float g_cq  [BATCH * M_PRO * INNER];   // ctx protein-side (attn^T @ v_pep)
__device__ float g_y1  [BATCH * N_PEP * INNER];   // ctx_p @ Wo_prot
__device__ float g_y2  [BATCH * M_PRO * INNER];   // ctx_q @ Wo_pep

// ---------------- generic 128x128x8 SGEMM tile ----------------
// TA: A stored as (K, M) row-major with leading dim lda (A[k*lda+m]); else (M,K).
// TB: B stored as (N, K) row-major with leading dim ldb (B[n*ldb+k]); else (K,N).
// Requires K % 8 == 0, N % 4 == 0, all base pointers & strides 16B-friendly
// (true for every use in this file). M/N bounds fully checked.
template <bool TA, bool TB>
__device__ __forceinline__ void gemm_tile(const float* __restrict__ A,
                                          const float* __restrict__ Bm,
                                          float* __restrict__ C,
                                          int M, int N, int K,
                                          int lda, int ldb, int ldc,
                                          float alpha, int row0, int col0)
{
    __shared__ float As[8][128];
    __shared__ float Bs[8][128];
    const int tid = threadIdx.x;
    const int tx = tid & 15;
    const int ty = tid >> 4;

    float acc[8][8];
#pragma unroll
    for (int i = 0; i < 8; i++)
#pragma unroll
        for (int j = 0; j < 8; j++) acc[i][j] = 0.0f;

    for (int k0 = 0; k0 < K; k0 += 8) {
        // ---- load A tile -> As[k][m] ----
        if (!TA) {
            int r  = tid >> 1;          // 0..127
            int kk = (tid & 1) * 4;     // 0 or 4
            float4 v = make_float4(0.f, 0.f, 0.f, 0.f);
            if (row0 + r < M)
                v = *(const float4*)&A[(long)(row0 + r) * lda + k0 + kk];
            As[kk + 0][r] = v.x; As[kk + 1][r] = v.y;
            As[kk + 2][r] = v.z; As[kk + 3][r] = v.w;
        } else {
            int kk = tid >> 5;          // 0..7
            int m0 = (tid & 31) * 4;    // 0..124
            float4 v = make_float4(0.f, 0.f, 0.f, 0.f);
            if (row0 + m0 < M)
                v = *(const float4*)&A[(long)(k0 + kk) * lda + row0 + m0];
            *(float4*)&As[kk][m0] = v;
        }
        // ---- load B tile -> Bs[k][n] ----
        if (!TB) {
            int kk = tid >> 5;
            int n0 = (tid & 31) * 4;
            float4 v = make_float4(0.f, 0.f, 0.f, 0.f);
            if (col0 + n0 < N)
                v = *(const float4*)&Bm[(long)(k0 + kk) * ldb + col0 + n0];
            *(float4*)&Bs[kk][n0] = v;
        } else {
            int n  = tid >> 1;
            int kk = (tid & 1) * 4;
            float4 v = make_float4(0.f, 0.f, 0.f, 0.f);
            if (col0 + n < N)
                v = *(const float4*)&Bm[(long)(col0 + n) * ldb + k0 + kk];
            Bs[kk + 0][n] = v.x; Bs[kk + 1][n] = v.y;
            Bs[kk + 2][n] = v.z; Bs[kk + 3][n] = v.w;
        }
        __syncthreads();

#pragma unroll
        for (int kk = 0; kk < 8; kk++) {
            float a[8], b[8];
#pragma unroll
            for (int i = 0; i < 8; i++) a[i] = As[kk][ty * 8 + i];
#pragma unroll
            for (int j = 0; j < 8; j++) b[j] = Bs[kk][tx * 8 + j];
#pragma unroll
            for (int i = 0; i < 8; i++)
#pragma unroll
                for (int j = 0; j < 8; j++)
                    acc[i][j] = fmaf(a[i], b[j], acc[i][j]);
        }
        __syncthreads();
    }

#pragma unroll
    for (int i = 0; i < 8; i++) {
        int r = row0 + ty * 8 + i;
        if (r >= M) continue;
#pragma unroll
        for (int j = 0; j < 8; j++) {
            int c = col0 + tx * 8 + j;
            if (c < N) C[(long)r * ldc + c] = alpha * acc[i][j];
        }
    }
}

// ---------------- kernel wrappers ----------------
__global__ void __launch_bounds__(256)
k_gemm_nn(const float* __restrict__ A, const float* __restrict__ Bm,
          float* __restrict__ C, int M, int N, int K,
          int lda, int ldb, int ldc, float alpha)
{
    gemm_tile<false, false>(A, Bm, C, M, N, K, lda, ldb, ldc, alpha,
                            blockIdx.y * 128, blockIdx.x * 128);
}

// scores: per (b,h): C[n,m] = SCALE * sum_d q[n,d] * k[m,d]
__global__ void __launch_bounds__(256)
k_scores(const float* __restrict__ q, const float* __restrict__ kb,
         float* __restrict__ attn)
{
    int z = blockIdx.z;          // b*8 + h
    int b = z >> 3, h = z & 7;
    const float* A  = q  + (long)b * N_PEP * INNER + h * DH;
    const float* Bm = kb + (long)b * M_PRO * INNER + h * DH;
    float* C = attn + (long)z * N_PEP * M_PRO;
    gemm_tile<false, true>(A, Bm, C, N_PEP, M_PRO, DH,
                           INNER, INNER, M_PRO, SCALE_F,
                           blockIdx.y * 128, blockIdx.x * 128);
}

// ctx_prot: per (b,h): C[n,d] = sum_m attn[n,m] * v_prot[m,d]
__global__ void __launch_bounds__(256)
k_ctxprot(const float* __restrict__ attn, const float* __restrict__ vprot,
          float* __restrict__ ctx)
{
    int z = blockIdx.z; int b = z >> 3, h = z & 7;
    const float* A  = attn  + (long)z * N_PEP * M_PRO;
    const float* Bm = vprot + (long)b * M_PRO * INNER + h * DH;
    float* C = ctx + (long)b * N_PEP * INNER + h * DH;
    gemm_tile<false, false>(A, Bm, C, N_PEP, DH, M_PRO,
                            M_PRO, INNER, INNER, 1.0f, 0, 0);
}

// ctx_pep: per (b,h): C[m,d] = sum_n attn[n,m] * v_pep[n,d]   (A transposed)
__global__ void __launch_bounds__(256)
k_ctxpep(const float* __restrict__ attn, const float* __restrict__ vpep,
         float* __restrict__ ctx)
{
    int z = blockIdx.z; int b = z >> 3, h = z & 7;
    const float* A  = attn + (long)z * N_PEP * M_PRO;  // (K=128, M=2048) layout
    const float* Bm = vpep + (long)b * N_PEP * INNER + h * DH;
    float* C = ctx + (long)b * M_PRO * INNER + h * DH;
    gemm_tile<true, false>(A, Bm, C, M_PRO, DH, N_PEP,
                           M_PRO, INNER, INNER, 1.0f,
                           blockIdx.y * 128, 0);
}

// masked softmax over m, in-place on attn region of d_out
__global__ void __launch_bounds__(256)
k_softmax(float* __restrict__ attn, const int* __restrict__ pmask,
          const int* __restrict__ promask)
{
    int row = blockIdx.x;             // b*8*128 + h*128 + n
    int n = row & (N_PEP - 1);
    int z = row / N_PEP;
    int b = z >> 3;
    float* p = attn + (long)row * M_PRO;
    const int row_valid = pmask[b * N_PEP + n];
    const int* pm = promask + b * M_PRO;
    const int tid = threadIdx.x;

    float vals[8];
    float mx = -INFINITY;
#pragma unroll
    for (int i = 0; i < 8; i++) {
        int c = tid + i * 256;
        float v = p[c];
        if (row_valid == 0 || pm[c] == 0) v = NEG_F;
        vals[i] = v;
        mx = fmaxf(mx, v);
    }
    __shared__ float red[256];
    red[tid] = mx; __syncthreads();
    for (int s = 128; s > 0; s >>= 1) {
        if (tid < s) red[tid] = fmaxf(red[tid], red[tid + s]);
        __syncthreads();
    }
    mx = red[0]; __syncthreads();

    float sum = 0.0f;
#pragma unroll
    for (int i = 0; i < 8; i++) { vals[i] = expf(vals[i] - mx); sum += vals[i]; }
    red[tid] = sum; __syncthreads();
    for (int s = 128; s > 0; s >>= 1) {
        if (tid < s) red[tid] += red[tid + s];
        __syncthreads();
    }
    float inv = 1.0f / red[0];
#pragma unroll
    for (int i = 0; i < 8; i++) p[tid + i * 256] = vals[i] * inv;
}

// out = LayerNorm(Y + bias + residual) * g + b
__global__ void __launch_bounds__(256)
k_ln(const float* __restrict__ Y, const float* __restrict__ bo,
     const float* __restrict__ resid, const float* __restrict__ g,
     const float* __restrict__ beta, float* __restrict__ out)
{
    int row = blockIdx.x;
    int tid = threadIdx.x;
    const float* y = Y + (long)row * INNER;
    const float* r = resid + (long)row * INNER;

    float x[3];
    float s = 0.0f;
#pragma unroll
    for (int i = 0; i < 3; i++) {
        int c = tid + i * 256;
        x[i] = y[c] + bo[c] + r[c];
        s += x[i];
    }
    __shared__ float red[256];
    red[tid] = s; __syncthreads();
    for (int st = 128; st > 0; st >>= 1) {
        if (tid < st) red[tid] += red[tid + st];
        __syncthreads();
    }
    float mu = red[0] * (1.0f / INNER); __syncthreads();

    float v = 0.0f;
#pragma unroll
    for (int i = 0; i < 3; i++) { float d = x[i] - mu; v += d * d; }
    red[tid] = v; __syncthreads();
    for (int st = 128; st > 0; st >>= 1) {
        if (tid < st) red[tid] += red[tid + st];
        __syncthreads();
    }
    float rstd = rsqrtf(red[0] * (1.0f / INNER) + EPS_F);
#pragma unroll
    for (int i = 0; i < 3; i++) {
        int c = tid + i * 256;
        out[(long)row * INNER + c] = (x[i] - mu) * rstd * g[c] + beta[c];
    }
}

// ---------------- launch ----------------
extern "C" void kernel_launch(void* const* d_in, const int* in_sizes, int n_in,
                              void* d_out, int out_size)
{
    const float* peptide = (const float*)d_in[0];
    const float* protein = (const float*)d_in[1];
    const int*   pmask   = (const int*)  d_in[2];
    const int*   promask = (const int*)  d_in[3];
    const float* Wq      = (const float*)d_in[4];
    const float* Wk      = (const float*)d_in[5];
    const float* Wvp     = (const float*)d_in[6];   // Wv_prot
    const float* Wvq     = (const float*)d_in[7];   // Wv_pep
    const float* Wop     = (const float*)d_in[8];   // Wo_prot
    const float* bop     = (const float*)d_in[9];
    const float* Woq     = (const float*)d_in[10];  // Wo_pep
    const float* boq     = (const float*)d_in[11];
    const float* lng     = (const float*)d_in[12];
    const float* lnb     = (const float*)d_in[13];

    float* out = (float*)d_out;
    float* out_prot = out;                                        // (16,128,768)
    float* out_pep  = out + (long)BATCH * N_PEP * INNER;          // (16,2048,768)
    float* attn     = out_pep + (long)BATCH * M_PRO * INNER;      // (16,8,128,2048)

    float *q, *k, *vp, *vq, *cp, *cq, *y1, *y2;
    cudaGetSymbolAddress((void**)&q,  g_q);
    cudaGetSymbolAddress((void**)&k,  g_k);
    cudaGetSymbolAddress((void**)&vp, g_vp);
    cudaGetSymbolAddress((void**)&vq, g_vq);
    cudaGetSymbolAddress((void**)&cp, g_cp);
    cudaGetSymbolAddress((void**)&cq, g_cq);
    cudaGetSymbolAddress((void**)&y1, g_y1);
    cudaGetSymbolAddress((void**)&y2, g_y2);

    const dim3 blk(256);

    // projections
    k_gemm_nn<<<dim3(6, 16),  blk>>>(peptide, Wq,  q,  BATCH * N_PEP, INNER, INNER, INNER, INNER, INNER, 1.0f);
    k_gemm_nn<<<dim3(6, 16),  blk>>>(peptide, Wvq, vq, BATCH * N_PEP, INNER, INNER, INNER, INNER, INNER, 1.0f);
    k_gemm_nn<<<dim3(6, 256), blk>>>(protein, Wk,  k,  BATCH * M_PRO, INNER, INNER, INNER, INNER, INNER, 1.0f);
    k_gemm_nn<<<dim3(6, 256), blk>>>(protein, Wvp, vp, BATCH * M_PRO, INNER, INNER, INNER, INNER, INNER, 1.0f);

    // attention scores + softmax (attn lives in d_out)
    k_scores <<<dim3(16, 1, BATCH * HEADS), blk>>>(q, k, attn);
    k_softmax<<<BATCH * HEADS * N_PEP, 256>>>(attn, pmask, promask);

    // context
    k_ctxprot<<<dim3(1, 1,  BATCH * HEADS), blk>>>(attn, vp, cp);
    k_ctxpep <<<dim3(1, 16, BATCH * HEADS), blk>>>(attn, vq, cq);

    // output projections
    k_gemm_nn<<<dim3(6, 16),  blk>>>(cp, Wop, y1, BATCH * N_PEP, INNER, INNER, INNER, INNER, INNER, 1.0f);
    k_gemm_nn<<<dim3(6, 256), blk>>>(cq, Woq, y2, BATCH * M_PRO, INNER, INNER, INNER, INNER, INNER, 1.0f);

    // bias + residual + layernorm
    k_ln<<<BATCH * N_PEP, 256>>>(y1, bop, peptide, lng, lnb, out_prot);
    k_ln<<<BATCH * M_PRO, 256>>>(y2, boq, protein, lng, lnb, out_pep);
}

// round 2
// speedup vs baseline: 2.7024x; 2.7024x over previous
#include <cuda_runtime.h>
#include <math.h>

#define BATCH   16
#define N_PEP   128
#define M_PRO   2048
#define HEADS   8
#define DH      96
#define INNER   768
#define SCALE_F 0.10206207261596577f   /* 96^-0.5 */
#define NEG_F   -1000000.0f
#define EPS_F   1e-5f

#define BM 128
#define BN 128
#define BK 32

// ---------------- scratch (device globals; no allocations) ----------------
__device__ float g_q   [BATCH * N_PEP * INNER];
__device__ float g_k   [BATCH * M_PRO * INNER];
__device__ float g_vp  [BATCH * M_PRO * INNER];
__device__ float g_vq  [BATCH * N_PEP * INNER];
__device__ float g_cp  [BATCH * N_PEP * INNER];
__device__ float g_cq  [BATCH * M_PRO * INNER];
__device__ float g_y1  [BATCH * N_PEP * INNER];
__device__ float g_y2  [BATCH * M_PRO * INNER];

// ---------------- tf32 mma helpers ----------------
__device__ __forceinline__ unsigned f2tf(float x) {
    unsigned r;
    asm("cvt.rna.tf32.f32 %0, %1;" : "=r"(r) : "f"(x));
    return r;
}

__device__ __forceinline__ void mma_tf32(float* c, const unsigned* a,
                                         unsigned b0, unsigned b1) {
    asm volatile(
        "mma.sync.aligned.m16n8k8.row.col.f32.tf32.tf32.f32 "
        "{%0,%1,%2,%3}, {%4,%5,%6,%7}, {%8,%9}, {%0,%1,%2,%3};"
        : "+f"(c[0]), "+f"(c[1]), "+f"(c[2]), "+f"(c[3])
        : "r"(a[0]), "r"(a[1]), "r"(a[2]), "r"(a[3]), "r"(b0), "r"(b1));
}

// ---------------- generic 128x128x32 tensor-core GEMM tile ----------------
// TA: A stored (K, M) row-major with leading dim lda; else (M, K).
// TB: B stored (N, K) row-major with leading dim ldb; else (K, N).
// Requires K % 32 == 0, N % 4 == 0 (true for every use here).
template <bool TA, bool TB>
__device__ __forceinline__ void gemm_mma(const float* __restrict__ A,
                                         const float* __restrict__ Bm,
                                         float* __restrict__ C,
                                         int M, int N, int K,
                                         int lda, int ldb, int ldc,
                                         float alpha, int row0, int col0)
{
    __shared__ float As[BM][BK + 4];   // [m][k], pad 4 -> conflict-free frag reads
    __shared__ float Bs[BK][BN + 4];   // [k][n], pad 4 -> conflict-free frag reads

    const int tid  = threadIdx.x;
    const int lane = tid & 31;
    const int wid  = tid >> 5;
    const int wm   = (wid >> 1) * 32;   // warp row offset: 0,32,64,96
    const int wn   = (wid & 1) * 64;    // warp col offset: 0,64

    float acc[2][8][4];
#pragma unroll
    for (int i = 0; i < 2; i++)
#pragma unroll
        for (int j = 0; j < 8; j++)
#pragma unroll
            for (int t = 0; t < 4; t++) acc[i][j][t] = 0.0f;

    for (int k0 = 0; k0 < K; k0 += BK) {
        // ---- load A tile -> As[m][k] ----
        if (!TA) {
#pragma unroll
            for (int r = 0; r < 4; r++) {
                int m  = (tid >> 3) + r * 32;
                int kk = (tid & 7) * 4;
                float4 v = make_float4(0.f, 0.f, 0.f, 0.f);
                if (row0 + m < M)
                    v = *(const float4*)&A[(long)(row0 + m) * lda + k0 + kk];
                *(float4*)&As[m][kk] = v;
            }
        } else {
            // A stored (K, M): coalesced reads across m, scalar smem writes
            int tm = tid & 127;
            int kh = (tid >> 7) * 16;
            bool mok = (row0 + tm < M);
#pragma unroll
            for (int kk = 0; kk < 16; kk++) {
                float v = mok ? A[(long)(k0 + kh + kk) * lda + row0 + tm] : 0.0f;
                As[tm][kh + kk] = v;
            }
        }
        // ---- load B tile -> Bs[k][n] ----
        if (!TB) {
#pragma unroll
            for (int it = 0; it < 4; it++) {
                int q  = tid + it * 256;
                int kk = q >> 5;
                int n4 = (q & 31) * 4;
                float4 v = make_float4(0.f, 0.f, 0.f, 0.f);
                if (col0 + n4 < N)
                    v = *(const float4*)&Bm[(long)(k0 + kk) * ldb + col0 + n4];
                *(float4*)&Bs[kk][n4] = v;
            }
        } else {
            // B stored (N, K): read float4 along k, transpose into Bs
#pragma unroll
            for (int it = 0; it < 4; it++) {
                int q  = tid + it * 256;
                int n  = q >> 3;
                int kq = (q & 7) * 4;
                float4 v = make_float4(0.f, 0.f, 0.f, 0.f);
                if (col0 + n < N)
                    v = *(const float4*)&Bm[(long)(col0 + n) * ldb + k0 + kq];
                Bs[kq + 0][n] = v.x; Bs[kq + 1][n] = v.y;
                Bs[kq + 2][n] = v.z; Bs[kq + 3][n] = v.w;
            }
        }
        __syncthreads();

        // ---- 4 k-steps of 8 ----
#pragma unroll
        for (int ks = 0; ks < 4; ks++) {
            const int kc = ks * 8;
            unsigned af[2][4];
            const int ar = wm + (lane >> 2);
            const int ac = kc + (lane & 3);
#pragma unroll
            for (int i = 0; i < 2; i++) {
                af[i][0] = f2tf(As[ar + i * 16][ac]);
                af[i][1] = f2tf(As[ar + i * 16 + 8][ac]);
                af[i][2] = f2tf(As[ar + i * 16][ac + 4]);
                af[i][3] = f2tf(As[ar + i * 16 + 8][ac + 4]);
            }
#pragma unroll
            for (int j = 0; j < 8; j++) {
                const int bn = wn + j * 8 + (lane >> 2);
                unsigned b0 = f2tf(Bs[kc + (lane & 3)][bn]);
                unsigned b1 = f2tf(Bs[kc + 4 + (lane & 3)][bn]);
                mma_tf32(acc[0][j], af[0], b0, b1);
                mma_tf32(acc[1][j], af[1], b0, b1);
            }
        }
        __syncthreads();
    }

    // ---- epilogue ----
#pragma unroll
    for (int i = 0; i < 2; i++) {
#pragma unroll
        for (int j = 0; j < 8; j++) {
            int r = row0 + wm + i * 16 + (lane >> 2);
            int c = col0 + wn + j * 8 + (lane & 3) * 2;
            if (r < M) {
                if (c < N)     C[(long)r * ldc + c]     = alpha * acc[i][j][0];
                if (c + 1 < N) C[(long)r * ldc + c + 1] = alpha * acc[i][j][1];
            }
            if (r + 8 < M) {
                if (c < N)     C[(long)(r + 8) * ldc + c]     = alpha * acc[i][j][2];
                if (c + 1 < N) C[(long)(r + 8) * ldc + c + 1] = alpha * acc[i][j][3];
            }
        }
    }
}

// ---------------- kernel wrappers ----------------
__global__ void __launch_bounds__(256)
k_gemm_nn(const float* __restrict__ A, const float* __restrict__ Bm,
          float* __restrict__ C, int M, int N, int K,
          int lda, int ldb, int ldc, float alpha)
{
    gemm_mma<false, false>(A, Bm, C, M, N, K, lda, ldb, ldc, alpha,
                           blockIdx.y * BM, blockIdx.x * BN);
}

__global__ void __launch_bounds__(256)
k_scores(const float* __restrict__ q, const float* __restrict__ kb,
         float* __restrict__ attn)
{
    int z = blockIdx.z;
    int b = z >> 3, h = z & 7;
    const float* A  = q  + (long)b * N_PEP * INNER + h * DH;
    const float* Bm = kb + (long)b * M_PRO * INNER + h * DH;
    float* C = attn + (long)z * N_PEP * M_PRO;
    gemm_mma<false, true>(A, Bm, C, N_PEP, M_PRO, DH,
                          INNER, INNER, M_PRO, SCALE_F,
                          blockIdx.y * BM, blockIdx.x * BN);
}

__global__ void __launch_bounds__(256)
k_ctxprot(const float* __restrict__ attn, const float* __restrict__ vprot,
          float* __restrict__ ctx)
{
    int z = blockIdx.z; int b = z >> 3, h = z & 7;
    const float* A  = attn  + (long)z * N_PEP * M_PRO;
    const float* Bm = vprot + (long)b * M_PRO * INNER + h * DH;
    float* C = ctx + (long)b * N_PEP * INNER + h * DH;
    gemm_mma<false, false>(A, Bm, C, N_PEP, DH, M_PRO,
                           M_PRO, INNER, INNER, 1.0f, 0, 0);
}

__global__ void __launch_bounds__(256)
k_ctxpep(const float* __restrict__ attn, const float* __restrict__ vpep,
         float* __restrict__ ctx)
{
    int z = blockIdx.z; int b = z >> 3, h = z & 7;
    const float* A  = attn + (long)z * N_PEP * M_PRO;   // (K=n, M=m) layout
    const float* Bm = vpep + (long)b * N_PEP * INNER + h * DH;
    float* C = ctx + (long)b * M_PRO * INNER + h * DH;
    gemm_mma<true, false>(A, Bm, C, M_PRO, DH, N_PEP,
                          M_PRO, INNER, INNER, 1.0f,
                          blockIdx.y * BM, 0);
}

// masked softmax over m, in-place on attn region of d_out
__global__ void __launch_bounds__(256)
k_softmax(float* __restrict__ attn, const int* __restrict__ pmask,
          const int* __restrict__ promask)
{
    int row = blockIdx.x;
    int n = row & (N_PEP - 1);
    int z = row / N_PEP;
    int b = z >> 3;
    float* p = attn + (long)row * M_PRO;
    const int row_valid = pmask[b * N_PEP + n];
    const int* pm = promask + b * M_PRO;
    const int tid = threadIdx.x;

    float vals[8];
    float mx = -INFINITY;
#pragma unroll
    for (int i = 0; i < 8; i++) {
        int c = tid + i * 256;
        float v = p[c];
        if (row_valid == 0 || pm[c] == 0) v = NEG_F;
        vals[i] = v;
        mx = fmaxf(mx, v);
    }
    __shared__ float red[256];
    red[tid] = mx; __syncthreads();
    for (int s = 128; s > 0; s >>= 1) {
        if (tid < s) red[tid] = fmaxf(red[tid], red[tid + s]);
        __syncthreads();
    }
    mx = red[0]; __syncthreads();

    float sum = 0.0f;
#pragma unroll
    for (int i = 0; i < 8; i++) { vals[i] = expf(vals[i] - mx); sum += vals[i]; }
    red[tid] = sum; __syncthreads();
    for (int s = 128; s > 0; s >>= 1) {
        if (tid < s) red[tid] += red[tid + s];
        __syncthreads();
    }
    float inv = 1.0f / red[0];
#pragma unroll
    for (int i = 0; i < 8; i++) p[tid + i * 256] = vals[i] * inv;
}

// out = LayerNorm(Y + bias + residual) * g + b
__global__ void __launch_bounds__(256)
k_ln(const float* __restrict__ Y, const float* __restrict__ bo,
     const float* __restrict__ resid, const float* __restrict__ g,
     const float* __restrict__ beta, float* __restrict__ out)
{
    int row = blockIdx.x;
    int tid = threadIdx.x;
    const float* y = Y + (long)row * INNER;
    const float* r = resid + (long)row * INNER;

    float x[3];
    float s = 0.0f;
#pragma unroll
    for (int i = 0; i < 3; i++) {
        int c = tid + i * 256;
        x[i] = y[c] + bo[c] + r[c];
        s += x[i];
    }
    __shared__ float red[256];
    red[tid] = s; __syncthreads();
    for (int st = 128; st > 0; st >>= 1) {
        if (tid < st) red[tid] += red[tid + st];
        __syncthreads();
    }
    float mu = red[0] * (1.0f / INNER); __syncthreads();

    float v = 0.0f;
#pragma unroll
    for (int i = 0; i < 3; i++) { float d = x[i] - mu; v += d * d; }
    red[tid] = v; __syncthreads();
    for (int st = 128; st > 0; st >>= 1) {
        if (tid < st) red[tid] += red[tid + st];
        __syncthreads();
    }
    float rstd = rsqrtf(red[0] * (1.0f / INNER) + EPS_F);
#pragma unroll
    for (int i = 0; i < 3; i++) {
        int c = tid + i * 256;
        out[(long)row * INNER + c] = (x[i] - mu) * rstd * g[c] + beta[c];
    }
}

// ---------------- launch ----------------
extern "C" void kernel_launch(void* const* d_in, const int* in_sizes, int n_in,
                              void* d_out, int out_size)
{
    const float* peptide = (const float*)d_in[0];
    const float* protein = (const float*)d_in[1];
    const int*   pmask   = (const int*)  d_in[2];
    const int*   promask = (const int*)  d_in[3];
    const float* Wq      = (const float*)d_in[4];
    const float* Wk      = (const float*)d_in[5];
    const float* Wvp     = (const float*)d_in[6];
    const float* Wvq     = (const float*)d_in[7];
    const float* Wop     = (const float*)d_in[8];
    const float* bop     = (const float*)d_in[9];
    const float* Woq     = (const float*)d_in[10];
    const float* boq     = (const float*)d_in[11];
    const float* lng     = (const float*)d_in[12];
    const float* lnb     = (const float*)d_in[13];

    float* out = (float*)d_out;
    float* out_prot = out;                                   // (16,128,768)
    float* out_pep  = out + (long)BATCH * N_PEP * INNER;     // (16,2048,768)
    float* attn     = out_pep + (long)BATCH * M_PRO * INNER; // (16,8,128,2048)

    float *q, *k, *vp, *vq, *cp, *cq, *y1, *y2;
    cudaGetSymbolAddress((void**)&q,  g_q);
    cudaGetSymbolAddress((void**)&k,  g_k);
    cudaGetSymbolAddress((void**)&vp, g_vp);
    cudaGetSymbolAddress((void**)&vq, g_vq);
    cudaGetSymbolAddress((void**)&cp, g_cp);
    cudaGetSymbolAddress((void**)&cq, g_cq);
    cudaGetSymbolAddress((void**)&y1, g_y1);
    cudaGetSymbolAddress((void**)&y2, g_y2);

    const dim3 blk(256);

    // projections
    k_gemm_nn<<<dim3(6, 16),  blk>>>(peptide, Wq,  q,  BATCH * N_PEP, INNER, INNER, INNER, INNER, INNER, 1.0f);
    k_gemm_nn<<<dim3(6, 16),  blk>>>(peptide, Wvq, vq, BATCH * N_PEP, INNER, INNER, INNER, INNER, INNER, 1.0f);
    k_gemm_nn<<<dim3(6, 256), blk>>>(protein, Wk,  k,  BATCH * M_PRO, INNER, INNER, INNER, INNER, INNER, 1.0f);
    k_gemm_nn<<<dim3(6, 256), blk>>>(protein, Wvp, vp, BATCH * M_PRO, INNER, INNER, INNER, INNER, INNER, 1.0f);

    // attention scores + softmax (attn lives in d_out)
    k_scores <<<dim3(16, 1, BATCH * HEADS), blk>>>(q, k, attn);
    k_softmax<<<BATCH * HEADS * N_PEP, 256>>>(attn, pmask, promask);

    // context
    k_ctxprot<<<dim3(1, 1,  BATCH * HEADS), blk>>>(attn, vp, cp);
    k_ctxpep <<<dim3(1, 16, BATCH * HEADS), blk>>>(attn, vq, cq);

    // output projections
    k_gemm_nn<<<dim3(6, 16),  blk>>>(cp, Wop, y1, BATCH * N_PEP, INNER, INNER, INNER, INNER, INNER, 1.0f);
    k_gemm_nn<<<dim3(6, 256), blk>>>(cq, Woq, y2, BATCH * M_PRO, INNER, INNER, INNER, INNER, INNER, 1.0f);

    // bias + residual + layernorm
    k_ln<<<BATCH * N_PEP, 256>>>(y1, bop, peptide, lng, lnb, out_prot);
    k_ln<<<BATCH * M_PRO, 256>>>(y2, boq, protein, lng, lnb, out_pep);
}